// round 4
// baseline (speedup 1.0000x reference)
#include <cuda_runtime.h>
#include <math.h>

#define BB 4
#define CC 32
#define NHEAD 4
#define HDIM 8
#define NN 32768
#define PP 64

// ---------------- scratch (static device memory; no allocations) ----------------
static __device__ float g_xt  [BB*NN*CC];   // tokens + pos  [b][n][c]
static __device__ float g_q   [BB*CC*NN];   // [b*32+c][n],  c = h*8+d
static __device__ float g_k   [BB*CC*NN];
static __device__ float g_vca [BB*CC*NN];
static __device__ float g_vsa [BB*CC*NN];
static __device__ float g_part[64*256*PP];  // split-K partials for EF projections
static __device__ float g_kproj[BB*CC*PP];
static __device__ float g_vproj[BB*CC*PP];
static __device__ float g_npart[8*16*80];   // gram/norm partials
static __device__ float g_qinv[BB*CC];
static __device__ float g_attnca[BB*NHEAD*HDIM*HDIM];
static __device__ float g_xsa [BB*CC*NN];   // [b][h][d][n]
static __device__ float g_xca [BB*CC*NN];
static __device__ float g_skip[BB*CC*NN];   // attn_skip [B][C][32][32][32]
static __device__ float g_y1  [BB*CC*NN];
static __device__ float g_y2  [BB*CC*NN];

// ---------------- K1: transpose+pos, layernorm, QKVV GEMM ----------------
__global__ __launch_bounds__(256) void k1_tok_ln_qkvv(
    const float* __restrict__ x, const float* __restrict__ pos,
    const float* __restrict__ lng, const float* __restrict__ lnb,
    const float* __restrict__ Wq)
{
    __shared__ float xts[32][33];
    __shared__ float Ws[32][128];
    int b  = blockIdx.x >> 10;
    int n0 = (blockIdx.x & 1023) << 5;
    int t  = threadIdx.x;

    for (int i = t; i < 32*128; i += 256) Ws[i >> 7][i & 127] = Wq[i];
    // load x tile coalesced along n
    for (int i = t; i < 1024; i += 256) {
        int j = i & 31, c = i >> 5;
        xts[j][c] = x[(b*CC + c)*NN + n0 + j];
    }
    __syncthreads();
    // add pos-embed (coalesced along c), write xt
    for (int i = t; i < 1024; i += 256) {
        int c = i & 31, j = i >> 5;
        float v = xts[j][c] + pos[(n0 + j)*CC + c];
        xts[j][c] = v;
        g_xt[(b*NN + n0 + j)*CC + c] = v;
    }
    __syncthreads();
    // layernorm over C=32: warp w handles tokens 4w..4w+3, lane = channel
    int w = t >> 5, lane = t & 31;
    for (int jj = 0; jj < 4; jj++) {
        int j = w*4 + jj;
        float v = xts[j][lane];
        float s = v, ss = v*v;
        #pragma unroll
        for (int o = 16; o > 0; o >>= 1) {
            s  += __shfl_xor_sync(0xffffffffu, s, o);
            ss += __shfl_xor_sync(0xffffffffu, ss, o);
        }
        float mu  = s * (1.0f/32.0f);
        float var = ss * (1.0f/32.0f) - mu*mu;
        float r   = rsqrtf(var + 1e-5f);
        xts[j][lane] = (v - mu) * r * lng[lane] + lnb[lane];
    }
    __syncthreads();
    // GEMM: warp w -> cols 16w..16w+15, lane = token
    float acc[16];
    #pragma unroll
    for (int i = 0; i < 16; i++) acc[i] = 0.f;
    int c0 = w * 16;
    #pragma unroll
    for (int kk = 0; kk < 32; kk++) {
        float xv = xts[lane][kk];
        #pragma unroll
        for (int i = 0; i < 16; i++) acc[i] += xv * Ws[kk][c0 + i];
    }
    #pragma unroll
    for (int i = 0; i < 16; i++) {
        int col   = c0 + i;
        int which = col >> 5;
        int ch    = col & 31;
        float* dst = (which == 0) ? g_q : (which == 1) ? g_k :
                     (which == 2) ? g_vca : g_vsa;
        dst[(b*CC + ch)*NN + n0 + lane] = acc[i];
    }
}

// ---------------- K2: EF projections (split-K GEMM, partial) ----------------
__global__ __launch_bounds__(128) void k2_proj_partial(const float* __restrict__ EFw)
{
    __shared__ __align__(16) float Ks[64][68];
    __shared__ __align__(16) float Es[64][68];
    int chunk = blockIdx.x;        // 0..63 (512 n each)
    int rg    = blockIdx.y;        // 0..3 (0,1 -> k rows; 2,3 -> v rows)
    int t     = threadIdx.x;
    const float* src = (rg < 2) ? g_k : g_vsa;
    int r0  = (rg & 1) * 64;
    int nb0 = chunk * 512;

    float acc[4][8];
    #pragma unroll
    for (int i = 0; i < 4; i++)
        #pragma unroll
        for (int j = 0; j < 8; j++) acc[i][j] = 0.f;

    int pb = (t & 7) * 8;
    int ro = (t >> 3) * 4;
    for (int st = 0; st < 8; st++) {
        int nb = nb0 + st*64;
        __syncthreads();
        for (int i = t; i < 64*64; i += 128) {
            int nn = i & 63, rr = i >> 6;
            Ks[rr][nn] = src[(r0 + rr)*NN + nb + nn];
            Es[rr][nn] = EFw[rr*NN + nb + nn];
        }
        __syncthreads();
        #pragma unroll 4
        for (int nn = 0; nn < 64; nn += 4) {
            float4 rv[4];
            #pragma unroll
            for (int i = 0; i < 4; i++)
                rv[i] = *reinterpret_cast<const float4*>(&Ks[ro + i][nn]);
            #pragma unroll
            for (int j = 0; j < 8; j++) {
                float4 e = *reinterpret_cast<const float4*>(&Es[pb + j][nn]);
                #pragma unroll
                for (int i = 0; i < 4; i++) {
                    acc[i][j] += rv[i].x*e.x + rv[i].y*e.y
                               + rv[i].z*e.z + rv[i].w*e.w;
                }
            }
        }
    }
    #pragma unroll
    for (int i = 0; i < 4; i++)
        #pragma unroll
        for (int j = 0; j < 8; j++)
            g_part[(chunk*256 + rg*64 + ro + i)*PP + pb + j] = acc[i][j];
}

__global__ __launch_bounds__(256) void k2_proj_reduce(const float* __restrict__ EFb)
{
    int idx = blockIdx.x * 256 + threadIdx.x;   // 0..16383
    int row = idx >> 6, p = idx & 63;
    float s = 0.f;
    for (int c = 0; c < 64; c++) s += g_part[(c*256 + row)*PP + p];
    s += EFb[p];
    if (row < 128) g_kproj[row*PP + p] = s;
    else           g_vproj[(row - 128)*PP + p] = s;
}

// ---------------- K3a: gram matrix + L2 norms (partial) ----------------
__global__ __launch_bounds__(256) void k3a_gram_partial()
{
    int split = blockIdx.x;   // 0..7
    int bh    = blockIdx.y;   // 0..15
    int t     = threadIdx.x;
    const float* qb = g_q + bh*8*NN;
    const float* kb = g_k + bh*8*NN;

    float v[80];
    #pragma unroll
    for (int i = 0; i < 80; i++) v[i] = 0.f;

    int nend = split*4096 + 4096;
    for (int n = split*4096 + t; n < nend; n += 256) {
        float qv[8], kv[8];
        #pragma unroll
        for (int d = 0; d < 8; d++) { qv[d] = qb[d*NN + n]; kv[d] = kb[d*NN + n]; }
        #pragma unroll
        for (int d = 0; d < 8; d++) {
            v[64 + d] += qv[d]*qv[d];
            v[72 + d] += kv[d]*kv[d];
            #pragma unroll
            for (int e = 0; e < 8; e++) v[d*8 + e] += qv[d]*kv[e];
        }
    }
    __shared__ float wsum[8][80];
    int w = t >> 5, lane = t & 31;
    #pragma unroll
    for (int i = 0; i < 80; i++) {
        float s = v[i];
        #pragma unroll
        for (int o = 16; o > 0; o >>= 1) s += __shfl_xor_sync(0xffffffffu, s, o);
        if (lane == 0) wsum[w][i] = s;
    }
    __syncthreads();
    if (t < 80) {
        float s = 0.f;
        #pragma unroll
        for (int ww = 0; ww < 8; ww++) s += wsum[ww][t];
        g_npart[(split*16 + bh)*80 + t] = s;
    }
}

// ---------------- K3a2: finalize norms + channel-attention softmax ----------------
__global__ __launch_bounds__(128) void k3a_finalize(const float* __restrict__ temp1)
{
    int bh = blockIdx.x;
    int t  = threadIdx.x;
    __shared__ float tot[80];
    __shared__ float qi[8], ki[8];
    if (t < 80) {
        float s = 0.f;
        #pragma unroll
        for (int sp = 0; sp < 8; sp++) s += g_npart[(sp*16 + bh)*80 + t];
        tot[t] = s;
    }
    __syncthreads();
    if (t < 8) {
        float qn = sqrtf(tot[64 + t]);
        float kn = sqrtf(tot[72 + t]);
        qi[t] = 1.0f / fmaxf(qn, 1e-12f);
        ki[t] = 1.0f / fmaxf(kn, 1e-12f);
        g_qinv[bh*8 + t] = qi[t];
    }
    __syncthreads();
    if (t < 8) {
        int h = bh & 3;
        float t1 = temp1[h];
        float sc[8];
        float m = -1e30f;
        #pragma unroll
        for (int e = 0; e < 8; e++) {
            sc[e] = tot[t*8 + e] * qi[t] * ki[e] * t1;
            m = fmaxf(m, sc[e]);
        }
        float sum = 0.f;
        #pragma unroll
        for (int e = 0; e < 8; e++) { sc[e] = __expf(sc[e] - m); sum += sc[e]; }
        float inv = 1.0f / sum;
        #pragma unroll
        for (int e = 0; e < 8; e++) g_attnca[bh*64 + t*8 + e] = sc[e]*inv;
    }
}

// ---------------- K3b: spatial attention per token + channel-attn apply ----------------
__global__ __launch_bounds__(128) void k3b_attn(const float* __restrict__ temp2)
{
    int bh = blockIdx.y;
    int n  = blockIdx.x * 128 + threadIdx.x;
    int h  = bh & 3;
    int t  = threadIdx.x;
    __shared__ float kq[8][64], vp[8][64], A[8][8];
    float t2 = temp2[h];
    for (int i = t; i < 512; i += 128) {
        int d = i >> 6, p = i & 63;
        kq[d][p] = g_qinv[bh*8 + d] * g_kproj[(bh*8 + d)*PP + p] * t2;
        vp[d][p] = g_vproj[(bh*8 + d)*PP + p];
    }
    if (t < 64) A[t >> 3][t & 7] = g_attnca[bh*64 + t];
    __syncthreads();

    int base = bh*8*NN + n;
    float qv[8];
    #pragma unroll
    for (int d = 0; d < 8; d++) qv[d] = g_q[base + d*NN];

    float s[64];
    #pragma unroll
    for (int p = 0; p < 64; p++) s[p] = qv[0]*kq[0][p];
    #pragma unroll
    for (int d = 1; d < 8; d++)
        #pragma unroll
        for (int p = 0; p < 64; p++) s[p] += qv[d]*kq[d][p];

    float m = s[0];
    #pragma unroll
    for (int p = 1; p < 64; p++) m = fmaxf(m, s[p]);
    float sum = 0.f;
    #pragma unroll
    for (int p = 0; p < 64; p++) { s[p] = __expf(s[p] - m); sum += s[p]; }
    float inv = 1.0f / sum;

    #pragma unroll
    for (int d = 0; d < 8; d++) {
        float o = 0.f;
        #pragma unroll
        for (int p = 0; p < 64; p++) o += s[p]*vp[d][p];
        g_xsa[base + d*NN] = o * inv;
    }
    // channel attention apply
    float vv[8];
    #pragma unroll
    for (int e = 0; e < 8; e++) vv[e] = g_vca[base + e*NN];
    #pragma unroll
    for (int d = 0; d < 8; d++) {
        float xc = 0.f;
        #pragma unroll
        for (int e = 0; e < 8; e++) xc += A[d][e]*vv[e];
        g_xca[base + d*NN] = xc;
    }
}

// ---------------- K4: scramble-gather, out1/out2 linears, gamma residual, transpose ----------------
__global__ __launch_bounds__(128) void k4_combine(
    const float* __restrict__ o1w, const float* __restrict__ o1b,
    const float* __restrict__ o2w, const float* __restrict__ o2b,
    const float* __restrict__ gamma)
{
    __shared__ float sa[32][33], ca[32][33], xtl[32][33];
    __shared__ float w1[16][32], w2[16][32], b1[16], b2[16], gm[32];
    int b  = blockIdx.x >> 10;
    int t0 = (blockIdx.x & 1023) << 5;   // 32 output tokens
    int t  = threadIdx.x;
    int dd   = t0 >> 12;
    int hh   = (t0 >> 10) & 3;
    int nsrc = (t0 & 1023) << 5;

    const float* sap = g_xsa + ((b*NHEAD + hh)*HDIM + dd)*NN + nsrc;
    for (int i = t; i < 1024; i += 128) sa[i >> 5][i & 31] = sap[i];
    for (int i = t; i < 1024; i += 128) {
        int c = i >> 5, ii = i & 31;
        ca[ii][c] = g_xca[(b*CC + c)*NN + t0 + ii];
    }
    for (int i = t; i < 1024; i += 128) {
        int ii = i >> 5, c = i & 31;
        xtl[ii][c] = g_xt[(b*NN + t0 + ii)*CC + c];
    }
    for (int i = t; i < 512; i += 128) {
        w1[i >> 5][i & 31] = o1w[i];
        w2[i >> 5][i & 31] = o2w[i];
    }
    if (t < 16) { b1[t] = o1b[t]; b2[t] = o2b[t]; }
    if (t < 32) gm[t] = gamma[t];
    __syncthreads();

    int ii = t & 31;   // token in tile
    int cg = t >> 5;   // 0..3 (channel group of 8)
    #pragma unroll
    for (int cc = 0; cc < 8; cc++) {
        int c = cg*8 + cc;
        float val;
        if (c < 16) {
            float s = b1[c];
            #pragma unroll
            for (int k = 0; k < 32; k++) s += sa[ii][k]*w1[c][k];
            val = s;
        } else {
            int j = c - 16;
            float s = b2[j];
            #pragma unroll
            for (int k = 0; k < 32; k++) s += ca[ii][k]*w2[j][k];
            val = s;
        }
        float r = xtl[ii][c] + gm[c]*val;
        g_skip[(b*CC + c)*NN + t0 + ii] = r;
    }
}

// ---------------- conv 3x3x3 + BN (+residual) + LeakyReLU ----------------
template<int MODE>
__global__ __launch_bounds__(128) void conv3_bn(
    const float* __restrict__ w,  const float* __restrict__ cb,
    const float* __restrict__ bg, const float* __restrict__ bb,
    const float* __restrict__ bm, const float* __restrict__ bv)
{
    __shared__ float xs[16][3][6][35];
    __shared__ float ws[16][32][3];
    __shared__ float scs[32], bss[32];
    const float* in  = (MODE == 1) ? g_skip : g_y1;
    float*       out = (MODE == 1) ? g_y1   : g_y2;
    const float* res = g_skip;

    int yg = blockIdx.x;       // 0..7
    int z  = blockIdx.y;       // 0..31
    int b  = blockIdx.z;       // 0..3
    int y0 = yg*4;
    int t  = threadIdx.x;
    if (t < 32) {
        float a = bg[t]*rsqrtf(bv[t] + 1e-5f);
        scs[t] = a;
        bss[t] = (cb[t] - bm[t])*a + bb[t];
    }
    int cob = (t & 7)*4;
    int xb  = ((t >> 3) & 3)*8;
    int ty  = t >> 5;

    float acc[4][8];
    #pragma unroll
    for (int c = 0; c < 4; c++)
        #pragma unroll
        for (int u = 0; u < 8; u++) acc[c][u] = 0.f;

    for (int pass = 0; pass < 2; pass++) {
        int cio = pass*16;
        __syncthreads();
        for (int fl = t; fl < 16*3*6*34; fl += 128) {
            int xx = fl % 34; int r2 = fl / 34;
            int yy = r2 % 6;  r2 /= 6;
            int zz = r2 % 3;  int ci = r2 / 3;
            int zg = z + zz - 1, ygl = y0 + yy - 1, xg = xx - 1;
            float v = 0.f;
            if ((unsigned)zg < 32u && (unsigned)ygl < 32u && (unsigned)xg < 32u)
                v = in[(((b*32 + cio + ci)*32 + zg)*32 + ygl)*32 + xg];
            xs[ci][zz][yy][xx] = v;
        }
        __syncthreads();
        for (int kz = 0; kz < 3; kz++)
        for (int ky = 0; ky < 3; ky++) {
            for (int fl = t; fl < 1536; fl += 128) {
                int kx = fl % 3; int r2 = fl / 3;
                int co = r2 & 31; int ci = r2 >> 5;
                ws[ci][co][kx] = w[(((co*32 + cio + ci)*3 + kz)*3 + ky)*3 + kx];
            }
            __syncthreads();
            #pragma unroll
            for (int ci = 0; ci < 16; ci++) {
                float xv[10];
                #pragma unroll
                for (int j = 0; j < 10; j++) xv[j] = xs[ci][kz][ty + ky][xb + j];
                #pragma unroll
                for (int c = 0; c < 4; c++) {
                    float w0 = ws[ci][cob + c][0];
                    float w1v = ws[ci][cob + c][1];
                    float w2v = ws[ci][cob + c][2];
                    #pragma unroll
                    for (int u = 0; u < 8; u++)
                        acc[c][u] += w0*xv[u] + w1v*xv[u + 1] + w2v*xv[u + 2];
                }
            }
            __syncthreads();
        }
    }
    #pragma unroll
    for (int c = 0; c < 4; c++) {
        int co = cob + c;
        int base = (((b*32 + co)*32 + z)*32 + (y0 + ty))*32 + xb;
        float a = scs[co], bo = bss[co];
        #pragma unroll
        for (int u = 0; u < 8; u++) {
            float v = acc[c][u]*a + bo;
            if (MODE == 1) {
                v = (v > 0.f) ? v : 0.01f*v;
            } else {
                v += res[base + u];
                v = (v > 0.f) ? v : 0.01f*v;
            }
            out[base + u] = v;
        }
    }
}

// ---------------- final: 1x1 conv residual ----------------
__global__ __launch_bounds__(256) void k_final(
    const float* __restrict__ wp, const float* __restrict__ bp,
    float* __restrict__ outp)
{
    __shared__ float ys[32][64];
    __shared__ float wsm[32][32];
    __shared__ float bsh[32];
    int b  = blockIdx.x >> 9;
    int n0 = (blockIdx.x & 511) << 6;
    int t  = threadIdx.x;
    for (int i = t; i < 2048; i += 256) {
        int ci = i >> 6, nn = i & 63;
        ys[ci][nn] = g_y2[(b*32 + ci)*NN + n0 + nn];
    }
    for (int i = t; i < 1024; i += 256) wsm[i >> 5][i & 31] = wp[i];
    if (t < 32) bsh[t] = bp[t];
    __syncthreads();
    int nn = t & 63;
    int cg = t >> 6;
    #pragma unroll
    for (int cc = 0; cc < 8; cc++) {
        int co = cg*8 + cc;
        float s = bsh[co];
        #pragma unroll
        for (int ci = 0; ci < 32; ci++) s += wsm[co][ci]*ys[ci][nn];
        int idx = (b*32 + co)*NN + n0 + nn;
        outp[idx] = g_skip[idx] + s;
    }
}

// ---------------- launch ----------------
extern "C" void kernel_launch(void* const* d_in, const int* in_sizes, int n_in,
                              void* d_out, int out_size)
{
    const float* x    = (const float*)d_in[0];
    const float* pos  = (const float*)d_in[1];
    const float* lng  = (const float*)d_in[2];
    const float* lnb  = (const float*)d_in[3];
    const float* gam  = (const float*)d_in[4];
    const float* Wq   = (const float*)d_in[5];
    const float* EFw  = (const float*)d_in[6];
    const float* EFb  = (const float*)d_in[7];
    const float* t1   = (const float*)d_in[8];
    const float* t2   = (const float*)d_in[9];
    const float* o1w  = (const float*)d_in[10];
    const float* o1b  = (const float*)d_in[11];
    const float* o2w  = (const float*)d_in[12];
    const float* o2b  = (const float*)d_in[13];
    const float* c1w  = (const float*)d_in[14];
    const float* c1b  = (const float*)d_in[15];
    const float* b1g  = (const float*)d_in[16];
    const float* b1b  = (const float*)d_in[17];
    const float* b1m  = (const float*)d_in[18];
    const float* b1v  = (const float*)d_in[19];
    const float* c2w  = (const float*)d_in[20];
    const float* c2b  = (const float*)d_in[21];
    const float* b2g  = (const float*)d_in[22];
    const float* b2b  = (const float*)d_in[23];
    const float* b2m  = (const float*)d_in[24];
    const float* b2v  = (const float*)d_in[25];
    const float* cpw  = (const float*)d_in[26];
    const float* cpb  = (const float*)d_in[27];
    float* outp = (float*)d_out;

    k1_tok_ln_qkvv<<<4096, 256>>>(x, pos, lng, lnb, Wq);
    k2_proj_partial<<<dim3(64, 4), 128>>>(EFw);
    k2_proj_reduce<<<64, 256>>>(EFb);
    k3a_gram_partial<<<dim3(8, 16), 256>>>();
    k3a_finalize<<<16, 128>>>(t1);
    k3b_attn<<<dim3(256, 16), 128>>>(t2);
    k4_combine<<<4096, 128>>>(o1w, o1b, o2w, o2b, gam);
    conv3_bn<1><<<dim3(8, 32, 4), 128>>>(c1w, c1b, b1g, b1b, b1m, b1v);
    conv3_bn<2><<<dim3(8, 32, 4), 128>>>(c2w, c2b, b2g, b2b, b2m, b2v);
    k_final<<<2048, 256>>>(cpw, cpb, outp);
}